// round 17
// baseline (speedup 1.0000x reference)
#include <cuda_runtime.h>
#include <cuda_fp16.h>
#include <mma.h>
#include <math.h>
#include <stdint.h>

using namespace nvcuda;

#define NFEAT 128
#define HID   64
#define NCLS  40
#define MAXN  100000
#define MAXE  600000
#define SCAN_CHUNK 4096
#define PADW 136                      // gemm1 smem row pad (fp16 elems)
#define PADA2 72                      // gemm2 A row pad (K=64)
#define PADB2 88                      // gemm2 B row pad (N=80)

// ---------------- scratch (padded for unguarded frag stores) -----
__device__ __half g_t1h[(size_t)(MAXN + 256) * 128];   // [x@W1l | x@W1r] fp16
__device__ __half g_t2h[(size_t)(MAXN + 128) * 80];    // [h@W2l | h@W2r] fp16
__device__ __half g_hh[(size_t)MAXN * 64];             // hidden, fp16
__device__ int   g_deg[MAXN];
__device__ int   g_cur[MAXN];
__device__ int   g_rowptr[MAXN + 1];
__device__ int   g_adj[MAXE];
__device__ int   g_bsum[32];
__device__ int   g_bflag[32];

// ---------------- side stream + events (created once at load) -------
static cudaStream_t g_s2;
static cudaEvent_t  g_evFork, g_evG1;
static struct _StreamInit {
    _StreamInit() {
        cudaStreamCreateWithFlags(&g_s2, cudaStreamNonBlocking);
        cudaEventCreateWithFlags(&g_evFork, cudaEventDisableTiming);
        cudaEventCreateWithFlags(&g_evG1,   cudaEventDisableTiming);
    }
} g_streamInit;

// ---------------- helpers ----------------
__device__ __forceinline__ void addh8(float* a, uint4 u) {
    __half2* h = (__half2*)&u;
    #pragma unroll
    for (int i = 0; i < 4; i++) {
        float2 f = __half22float2(h[i]);
        a[2 * i]     += f.x;
        a[2 * i + 1] += f.y;
    }
}

// convert a 16x16 float accumulator fragment to fp16 and store to global.
// scr: per-warp 16x20 float scratch in smem (warp-private).
template <typename FragT>
__device__ __forceinline__ void frag_store_f16(float* scr, const FragT& acc,
                                               __half* dst, int ldm_h, int lane) {
    wmma::store_matrix_sync(scr, acc, 20, wmma::mem_row_major);
    __syncwarp();
    int r = lane >> 1, c8 = (lane & 1) * 8;
    const float* sp = scr + r * 20 + c8;
    __half2 h0 = __floats2half2_rn(sp[0], sp[1]);
    __half2 h1 = __floats2half2_rn(sp[2], sp[3]);
    __half2 h2 = __floats2half2_rn(sp[4], sp[5]);
    __half2 h3 = __floats2half2_rn(sp[6], sp[7]);
    uint4 v = make_uint4(*reinterpret_cast<uint32_t*>(&h0),
                         *reinterpret_cast<uint32_t*>(&h1),
                         *reinterpret_cast<uint32_t*>(&h2),
                         *reinterpret_cast<uint32_t*>(&h3));
    *(uint4*)(dst + (size_t)r * ldm_h + c8) = v;
    __syncwarp();
}

// ---------------- per-block inline dtype detect ----------------
__device__ __forceinline__ int detect_is64(const void* ei, int E, int N,
                                           int tid, int* s_flag) {
    if (tid < 32) {
        int samples = (E < 32) ? E : 32;
        bool bad = false;
        if (tid < samples) {
            long long v = ((const long long*)ei)[tid];
            bad = (v < 0 || v >= (long long)N);
        }
        unsigned m = __ballot_sync(0xffffffffu, bad);
        if (tid == 0) *s_flag = (m == 0u) ? 1 : 0;
    }
    __syncthreads();
    return *s_flag;
}

__device__ __forceinline__ int load_idx2(const void* ei, int pos, int is64) {
    if (is64) return (int)((const long long*)ei)[pos];
    return ((const int*)ei)[pos];
}

// g_deg is zero here (module load / re-zeroed by k_scan every call)
__global__ void k_hist(const void* __restrict__ ei, int E, int N) {
    __shared__ int s_flag;
    int is64 = detect_is64(ei, E, N, threadIdx.x, &s_flag);
    int half = (E + 1) >> 1;
    int e = blockIdx.x * blockDim.x + threadIdx.x;
    int d0 = -1, d1 = -1;
    if (e < half)        d0 = min(max(load_idx2(ei, E + e, is64), 0), N - 1);
    if (e + half < E)    d1 = min(max(load_idx2(ei, E + e + half, is64), 0), N - 1);
    if (d0 >= 0) atomicAdd(&g_deg[d0], 1);
    if (d1 >= 0) atomicAdd(&g_deg[d1], 1);
}

// ---- single-pass scan with decoupled block-sum lookback ----
__global__ void k_scan(int n) {
    const int tid = threadIdx.x, lane = tid & 31, wid = tid >> 5;
    const int bid = blockIdx.x;
    __shared__ int wsum[32];
    __shared__ int s_off;
    int idx = bid * SCAN_CHUNK + tid * 4;
    int v0 = 0, v1 = 0, v2 = 0, v3 = 0;
    if (idx + 0 < n) { v0 = g_deg[idx + 0]; g_deg[idx + 0] = 0; }
    if (idx + 1 < n) { v1 = g_deg[idx + 1]; g_deg[idx + 1] = 0; }
    if (idx + 2 < n) { v2 = g_deg[idx + 2]; g_deg[idx + 2] = 0; }
    if (idx + 3 < n) { v3 = g_deg[idx + 3]; g_deg[idx + 3] = 0; }
    int s = v0 + v1 + v2 + v3;
    int sc = s;
    #pragma unroll
    for (int d = 1; d < 32; d <<= 1) {
        int t = __shfl_up_sync(0xffffffffu, sc, d);
        if (lane >= d) sc += t;
    }
    if (lane == 31) wsum[wid] = sc;
    __syncthreads();
    if (wid == 0) {
        int ws = wsum[lane];
        #pragma unroll
        for (int d = 1; d < 32; d <<= 1) {
            int t = __shfl_up_sync(0xffffffffu, ws, d);
            if (lane >= d) ws += t;
        }
        wsum[lane] = ws;
    }
    __syncthreads();
    int warp_excl = (wid == 0) ? 0 : wsum[wid - 1];
    int excl = warp_excl + (sc - s);

    if (tid == 1023) {
        g_bsum[bid] = warp_excl + sc;
        __threadfence();
        atomicExch(&g_bflag[bid], 1);
    }
    if (tid < 32) {
        int acc = 0;
        for (int j = lane; j < bid; j += 32) {
            while (atomicAdd(&g_bflag[j], 0) == 0) {}
            acc += atomicAdd(&g_bsum[j], 0);
        }
        #pragma unroll
        for (int d = 16; d > 0; d >>= 1)
            acc += __shfl_down_sync(0xffffffffu, acc, d);
        if (lane == 0) s_off = acc;
    }
    __syncthreads();
    int off = s_off + excl;
    int p0 = off + v0, p1 = p0 + v1, p2 = p1 + v2, p3 = p2 + v3;
    if (idx + 0 < n) g_rowptr[idx + 1] = p0;
    if (idx + 1 < n) g_rowptr[idx + 2] = p1;
    if (idx + 2 < n) g_rowptr[idx + 3] = p2;
    if (idx + 3 < n) g_rowptr[idx + 4] = p3;
    if (bid == 0 && tid == 0) g_rowptr[0] = 0;
}

// g_cur is zero here (module load / reset by final k_finish2)
__global__ void k_fill(const void* __restrict__ ei, int E, int N) {
    __shared__ int s_flag;
    int is64 = detect_is64(ei, E, N, threadIdx.x, &s_flag);
    if (blockIdx.x == 0 && threadIdx.x < 32) g_bflag[threadIdx.x] = 0;
    int half = (E + 1) >> 1;
    int e = blockIdx.x * blockDim.x + threadIdx.x;
    if (e < half) {
        int dst = min(max(load_idx2(ei, E + e, is64), 0), N - 1);
        int src = min(max(load_idx2(ei, e, is64), 0), N - 1);
        int pos = g_rowptr[dst] + atomicAdd(&g_cur[dst], 1);
        if (pos < E) g_adj[pos] = src;
    }
    if (e + half < E) {
        int dst = min(max(load_idx2(ei, E + e + half, is64), 0), N - 1);
        int src = min(max(load_idx2(ei, e + half, is64), 0), N - 1);
        int pos = g_rowptr[dst] + atomicAdd(&g_cur[dst], 1);
        if (pos < E) g_adj[pos] = src;
    }
}

// ------------- GEMM1, persistent, fp16 in/out: T1h = X @ [W1l|W1r] ------------
// W converted fp32->fp16 in-kernel (no wsplit dependency).
// Epilogue scratch aliases the A-tile smem region (dead after MMA loop).
#define GEMM1_SMEM (2 * 128 * PADW * 2)

__global__ void __launch_bounds__(256, 2)
k_gemm1_wmma(const float* __restrict__ X,
             const float* __restrict__ W1l, const float* __restrict__ W1r,
             __half* __restrict__ T, int n) {
    extern __shared__ char smraw[];
    __half* Wh = (__half*)smraw;                  // [128][PADW]
    __half* Ah = Wh + 128 * PADW;                 // [128][PADW]
    const int tid = threadIdx.x, wid = tid >> 5, lane = tid & 31;
    float* scr = (float*)Ah + wid * 320;          // aliases A (used post-MMA only)

    // W: convert 128x128 fp32 -> fp16 smem (4096 float4 slots)
    #pragma unroll
    for (int it = 0; it < 16; it++) {
        int p = it * 256 + tid;
        int k = p >> 5, cq = p & 31;
        const float* src = (cq < 16) ? (W1l + k * 64 + cq * 4)
                                     : (W1r + k * 64 + (cq - 16) * 4);
        float4 v = *(const float4*)src;
        __half2 h01 = __floats2half2_rn(v.x, v.y);
        __half2 h23 = __floats2half2_rn(v.z, v.w);
        uint32_t* w = (uint32_t*)(Wh + k * PADW + cq * 4);
        w[0] = *reinterpret_cast<uint32_t*>(&h01);
        w[1] = *reinterpret_cast<uint32_t*>(&h23);
    }

    const int m0 = (wid & 1) * 64;
    const int n0 = (wid >> 1) * 32;
    const int ntiles = (n + 127) >> 7;

    for (int t = blockIdx.x; t < ntiles; t += gridDim.x) {
        const int row0 = t << 7;
        __syncthreads();               // epilogue/scratch done; W ready (1st iter)
        // convert X tile (128 rows x 128 cols): 4096 float4 slots
        #pragma unroll 4
        for (int it = 0; it < 16; it++) {
            int p = it * 256 + tid;
            int r = p >> 5, cq = p & 31;
            float4 v = make_float4(0.f, 0.f, 0.f, 0.f);
            if (row0 + r < n) v = ((const float4*)(X + (size_t)(row0 + r) * 128))[cq];
            __half2 h01 = __floats2half2_rn(v.x, v.y);
            __half2 h23 = __floats2half2_rn(v.z, v.w);
            uint32_t* a = (uint32_t*)(Ah + r * PADW + cq * 4);
            a[0] = *reinterpret_cast<uint32_t*>(&h01);
            a[1] = *reinterpret_cast<uint32_t*>(&h23);
        }
        __syncthreads();

        wmma::fragment<wmma::accumulator, 16, 16, 16, float> acc[4][2];
        #pragma unroll
        for (int r = 0; r < 4; r++)
            #pragma unroll
            for (int c = 0; c < 2; c++) wmma::fill_fragment(acc[r][c], 0.f);

        #pragma unroll
        for (int k = 0; k < 128; k += 16) {
            wmma::fragment<wmma::matrix_b, 16, 16, 16, __half, wmma::row_major> b[2];
            wmma::load_matrix_sync(b[0], Wh + k * PADW + n0,      PADW);
            wmma::load_matrix_sync(b[1], Wh + k * PADW + n0 + 16, PADW);
            #pragma unroll
            for (int r = 0; r < 4; r++) {
                wmma::fragment<wmma::matrix_a, 16, 16, 16, __half, wmma::row_major> a;
                wmma::load_matrix_sync(a, Ah + (m0 + r * 16) * PADW + k, PADW);
                wmma::mma_sync(acc[r][0], a, b[0], acc[r][0]);
                wmma::mma_sync(acc[r][1], a, b[1], acc[r][1]);
            }
        }

        __syncthreads();               // all A reads done -> safe to reuse as scratch
        #pragma unroll
        for (int r = 0; r < 4; r++)
            #pragma unroll
            for (int c = 0; c < 2; c++)
                frag_store_f16(scr, acc[r][c],
                               T + (size_t)(row0 + m0 + r * 16) * 128 + n0 + c * 16,
                               128, lane);
    }
}

// -------- finish layer1: gather t1h + mean + bias + sigmoid -> h (fp16) -------
__global__ void k_finish1(const __half* __restrict__ T, const float* __restrict__ bias,
                          int n) {
    int gid = blockIdx.x * blockDim.x + threadIdx.x;
    int node = gid >> 3;
    int q = gid & 7;
    if (node >= n) return;
    int s = g_rowptr[node], e = g_rowptr[node + 1];
    float a0[8] = {0,0,0,0,0,0,0,0};
    float a1[8] = {0,0,0,0,0,0,0,0};
    float a2[8] = {0,0,0,0,0,0,0,0};
    float a3[8] = {0,0,0,0,0,0,0,0};
    int p = s;
    for (; p + 3 < e; p += 4) {
        int j0 = g_adj[p], j1 = g_adj[p + 1], j2 = g_adj[p + 2], j3 = g_adj[p + 3];
        uint4 u0 = *(const uint4*)(T + (size_t)j0 * 128 + q * 8);
        uint4 u1 = *(const uint4*)(T + (size_t)j1 * 128 + q * 8);
        uint4 u2 = *(const uint4*)(T + (size_t)j2 * 128 + q * 8);
        uint4 u3 = *(const uint4*)(T + (size_t)j3 * 128 + q * 8);
        addh8(a0, u0); addh8(a1, u1); addh8(a2, u2); addh8(a3, u3);
    }
    for (; p < e; p++) {
        uint4 u = *(const uint4*)(T + (size_t)g_adj[p] * 128 + q * 8);
        addh8(a0, u);
    }
    #pragma unroll
    for (int i = 0; i < 8; i++) a0[i] += a1[i] + a2[i] + a3[i];
    float inv = 1.f / fmaxf((float)(e - s), 1.f);
    uint4 ru = *(const uint4*)(T + (size_t)node * 128 + 64 + q * 8);
    float rr[8] = {0,0,0,0,0,0,0,0};
    addh8(rr, ru);
    float4 b0 = *(const float4*)(bias + q * 8);
    float4 b1v = *(const float4*)(bias + q * 8 + 4);
    float bv[8] = {b0.x, b0.y, b0.z, b0.w, b1v.x, b1v.y, b1v.z, b1v.w};
    float o[8];
    #pragma unroll
    for (int i = 0; i < 8; i++) {
        float v = fmaf(a0[i], inv, rr[i] + bv[i]);
        o[i] = 1.f / (1.f + expf(-v));
    }
    __half2 h0 = __floats2half2_rn(o[0], o[1]);
    __half2 h1 = __floats2half2_rn(o[2], o[3]);
    __half2 h2 = __floats2half2_rn(o[4], o[5]);
    __half2 h3 = __floats2half2_rn(o[6], o[7]);
    *(uint4*)(g_hh + (size_t)node * 64 + q * 8) =
        make_uint4(*reinterpret_cast<uint32_t*>(&h0), *reinterpret_cast<uint32_t*>(&h1),
                   *reinterpret_cast<uint32_t*>(&h2), *reinterpret_cast<uint32_t*>(&h3));
}

// ------------- GEMM2, persistent, fp16 in/out: T2h = H @ [W2l|W2r] ------------
// W2 converted in-kernel; epilogue scratch aliases the A-tile region.
#define GEMM2_SMEM ((64 * PADB2 + 128 * PADA2) * 2)

__global__ void __launch_bounds__(320, 2)
k_gemm2_wmma(const float* __restrict__ W2l, const float* __restrict__ W2r,
             __half* __restrict__ T, int n) {
    extern __shared__ char smraw[];
    __half* Wh = (__half*)smraw;                   // [64][PADB2]
    __half* Ah = Wh + 64 * PADB2;                  // [128][PADA2]
    const int tid = threadIdx.x, wid = tid >> 5, lane = tid & 31;
    float* scr = (float*)Ah + wid * 320;           // aliases A (post-MMA only)

    // W2: convert 64x80 fp32 -> fp16 smem (1280 float4 slots)
    for (int p = tid; p < 1280; p += 320) {
        int k = p / 20, cq = p % 20;
        const float* src = (cq < 10) ? (W2l + k * 40 + cq * 4)
                                     : (W2r + k * 40 + (cq - 10) * 4);
        float4 v = *(const float4*)src;
        __half2 h01 = __floats2half2_rn(v.x, v.y);
        __half2 h23 = __floats2half2_rn(v.z, v.w);
        uint32_t* w = (uint32_t*)(Wh + k * PADB2 + cq * 4);
        w[0] = *reinterpret_cast<uint32_t*>(&h01);
        w[1] = *reinterpret_cast<uint32_t*>(&h23);
    }

    const int n0 = (wid % 5) * 16;
    const int m0 = (wid / 5) * 64;
    const int ntiles = (n + 127) >> 7;

    for (int t = blockIdx.x; t < ntiles; t += gridDim.x) {
        const int row0 = t << 7;
        __syncthreads();
        for (int p = tid; p < 2048; p += 320) {
            int r = p >> 4, cq = p & 15;
            uint2 hv = make_uint2(0u, 0u);
            if (row0 + r < n)
                hv = *(const uint2*)(g_hh + (size_t)(row0 + r) * 64 + cq * 4);
            *(uint2*)(Ah + r * PADA2 + cq * 4) = hv;
        }
        __syncthreads();

        wmma::fragment<wmma::accumulator, 16, 16, 16, float> acc[4];
        #pragma unroll
        for (int r = 0; r < 4; r++) wmma::fill_fragment(acc[r], 0.f);

        #pragma unroll
        for (int k = 0; k < 64; k += 16) {
            wmma::fragment<wmma::matrix_b, 16, 16, 16, __half, wmma::row_major> b;
            wmma::load_matrix_sync(b, Wh + k * PADB2 + n0, PADB2);
            #pragma unroll
            for (int r = 0; r < 4; r++) {
                wmma::fragment<wmma::matrix_a, 16, 16, 16, __half, wmma::row_major> a;
                wmma::load_matrix_sync(a, Ah + (m0 + r * 16) * PADA2 + k, PADA2);
                wmma::mma_sync(acc[r], a, b, acc[r]);
            }
        }

        __syncthreads();               // A reads done -> reuse as scratch
        #pragma unroll
        for (int r = 0; r < 4; r++)
            frag_store_f16(scr, acc[r],
                           T + (size_t)(row0 + m0 + r * 16) * 80 + n0, 80, lane);
    }
}

// -------- final: aggregate t2h + mean + residual + bias -> out (fp32) --------
__global__ void k_finish2(const __half* __restrict__ T, const float* __restrict__ bias,
                          float* __restrict__ out, int n) {
    int gid = blockIdx.x * blockDim.x + threadIdx.x;
    int node = gid / 5;
    int q = gid - node * 5;
    if (node >= n) return;
    int s = g_rowptr[node], e = g_rowptr[node + 1];
    float a0[8] = {0,0,0,0,0,0,0,0};
    float a1[8] = {0,0,0,0,0,0,0,0};
    float a2[8] = {0,0,0,0,0,0,0,0};
    float a3[8] = {0,0,0,0,0,0,0,0};
    int p = s;
    for (; p + 3 < e; p += 4) {
        int j0 = g_adj[p], j1 = g_adj[p + 1], j2 = g_adj[p + 2], j3 = g_adj[p + 3];
        uint4 u0 = *(const uint4*)(T + (size_t)j0 * 80 + q * 8);
        uint4 u1 = *(const uint4*)(T + (size_t)j1 * 80 + q * 8);
        uint4 u2 = *(const uint4*)(T + (size_t)j2 * 80 + q * 8);
        uint4 u3 = *(const uint4*)(T + (size_t)j3 * 80 + q * 8);
        addh8(a0, u0); addh8(a1, u1); addh8(a2, u2); addh8(a3, u3);
    }
    for (; p < e; p++) {
        uint4 u = *(const uint4*)(T + (size_t)g_adj[p] * 80 + q * 8);
        addh8(a0, u);
    }
    #pragma unroll
    for (int i = 0; i < 8; i++) a0[i] += a1[i] + a2[i] + a3[i];
    float inv = 1.f / fmaxf((float)(e - s), 1.f);
    uint4 ru = *(const uint4*)(T + (size_t)node * 80 + 40 + q * 8);
    float rr[8] = {0,0,0,0,0,0,0,0};
    addh8(rr, ru);
    float4 b0 = *(const float4*)(bias + q * 8);
    float4 b1v = *(const float4*)(bias + q * 8 + 4);
    float bv[8] = {b0.x, b0.y, b0.z, b0.w, b1v.x, b1v.y, b1v.z, b1v.w};
    float o[8];
    #pragma unroll
    for (int i = 0; i < 8; i++)
        o[i] = fmaf(a0[i], inv, rr[i] + bv[i]);
    float* dst = out + (size_t)node * 40 + q * 8;
    *(float4*)(dst + 0) = make_float4(o[0], o[1], o[2], o[3]);
    *(float4*)(dst + 4) = make_float4(o[4], o[5], o[6], o[7]);
    if (q == 0) g_cur[node] = 0;   // reset for next call
}

// ---------------- launch ----------------
extern "C" void kernel_launch(void* const* d_in, const int* in_sizes, int n_in,
                              void* d_out, int out_size) {
    const float* x   = (const float*)d_in[0];
    const void*  ei  = d_in[1];
    const float* W1l = (const float*)d_in[2];
    const float* b1  = (const float*)d_in[3];
    const float* W1r = (const float*)d_in[4];
    const float* W2l = (const float*)d_in[5];
    const float* b2  = (const float*)d_in[6];
    const float* W2r = (const float*)d_in[7];
    float* out = (float*)d_out;

    const int N = in_sizes[0] / NFEAT;
    const int E = in_sizes[1] / 2;
    const int NB = (N + SCAN_CHUNK - 1) / SCAN_CHUNK;
    const int EH = ((E + 1) / 2 + 255) / 256;

    void *t1p, *t2p;
    cudaGetSymbolAddress(&t1p, g_t1h);
    cudaGetSymbolAddress(&t2p, g_t2h);

    cudaFuncSetAttribute(k_gemm1_wmma, cudaFuncAttributeMaxDynamicSharedMemorySize, GEMM1_SMEM);
    cudaFuncSetAttribute(k_gemm2_wmma, cudaFuncAttributeMaxDynamicSharedMemorySize, GEMM2_SMEM);

    int g1 = 296;
    int nt1 = (N + 127) / 128;
    if (g1 > nt1) g1 = nt1;
    int g2 = 296;
    if (g2 > (N + 127) / 128) g2 = (N + 127) / 128;

    // fork: side stream = GEMM1 (starts immediately); main = graph build
    cudaEventRecord(g_evFork, 0);
    cudaStreamWaitEvent(g_s2, g_evFork, 0);

    k_gemm1_wmma<<<g1, 256, GEMM1_SMEM, g_s2>>>(x, W1l, W1r, (__half*)t1p, N);  // side
    k_hist<<<EH, 256>>>(ei, E, N);                                              // main
    k_scan<<<NB, 1024>>>(N);
    k_fill<<<EH, 256>>>(ei, E, N);

    // join
    cudaEventRecord(g_evG1, g_s2);
    cudaStreamWaitEvent(0, g_evG1, 0);

    // tail
    int tot1 = N * 8;
    k_finish1<<<(tot1 + 255) / 256, 256>>>((const __half*)t1p, b1, N);
    k_gemm2_wmma<<<g2, 320, GEMM2_SMEM>>>(W2l, W2r, (__half*)t2p, N);
    int tot2 = N * 5;
    k_finish2<<<(tot2 + 255) / 256, 256>>>((const __half*)t2p, b2, out, N);
}